// round 3
// baseline (speedup 1.0000x reference)
#include <cuda_runtime.h>
#include <cuda_bf16.h>
#include <mma.h>
using namespace nvcuda;

// Problem constants
#define NMAX   50000
#define EMAX   800000
#define TOTMAX (EMAX + NMAX)
#define GRAPHS 256
#define HC     256      // H*C
#define KIN    300      // n_in
#define FOUT   768      // nout

// ---------------- scratch (device globals; no allocation) ----------------
__device__ float  g_h[NMAX * HC];          // node features after linear [N,256]
__device__ float  g_asrc[NMAX * 4];        // per-node src attention logits [N,4]
__device__ float  g_adst[NMAX * 4];        // per-node dst attention logits [N,4]
__device__ float  g_e[TOTMAX * 4];         // per-edge exp(leaky(logit)) [E+N,4]
__device__ int    g_count[NMAX];           // in-degree (incl self-loop)
__device__ int    g_scanex[NMAX];          // per-chunk exclusive scan
__device__ int    g_bsum[64];              // chunk totals -> chunk offsets
__device__ int    g_rowoff[NMAX];          // CSR row offsets
__device__ int    g_cursor[NMAX];          // fill cursors
__device__ int    g_csrc[TOTMAX];          // CSR-ordered src ids
__device__ float4 g_cee[TOTMAX];           // CSR-ordered exp weights (per head)
__device__ float  g_pool[GRAPHS * HC];     // per-graph sums [G,256]
__device__ float  g_cnt[GRAPHS];           // per-graph node counts

// ---------------- 0: init scratch ----------------
__global__ void init_kernel(int M) {
    int i = blockIdx.x * blockDim.x + threadIdx.x;
    if (i < M)            g_count[i] = 0;
    if (i < GRAPHS * HC)  g_pool[i]  = 0.0f;
    if (i < GRAPHS)       g_cnt[i]   = 0.0f;
}

// ---------------- 1: h = x @ lin_w via bf16-split tensor cores ----------------
// D = Ah*Bh + Ah*Bl + Al*Bh (fp32 accum) ~= fp32 GEMM to ~2^-16.
// Block tile 128x128, BKF=32 fp32 k per chunk, 8 warps (4x2), warp tile 32x64.
#define BM 128
#define BKF 32
#define KP 40     // padded A smem k-stride (bf16 elems) -> 80B rows, conflict-free ldmatrix
#define NP 136    // padded B smem n-stride (bf16 elems) -> 272B rows, conflict-free ldmatrix
// smem layout (bytes): Ah[128*KP*2]=10240 | Al 10240 | Bh[32*NP*2]=8704 | Bl 8704 = 37888
#define SM_AH 0
#define SM_AL 10240
#define SM_BH 20480
#define SM_BL 29184
#define SM_TOT 37888

__global__ __launch_bounds__(256)
void gemm_h_kernel(const float* __restrict__ X,
                   const float* __restrict__ W,
                   const float* __restrict__ att_s,
                   const float* __restrict__ att_d,
                   int M) {
    __shared__ __align__(16) unsigned char smem_raw[SM_TOT];
    __shared__ float s_as[128], s_ad[128];

    __nv_bfloat16* Ah = (__nv_bfloat16*)(smem_raw + SM_AH);
    __nv_bfloat16* Al = (__nv_bfloat16*)(smem_raw + SM_AL);
    __nv_bfloat16* Bh = (__nv_bfloat16*)(smem_raw + SM_BH);
    __nv_bfloat16* Bl = (__nv_bfloat16*)(smem_raw + SM_BL);

    const int bx   = blockIdx.x;          // 0..1 -> N offset bx*128 (heads bx*2, bx*2+1)
    const int row0 = blockIdx.y * BM;
    const int tid  = threadIdx.x;
    const int warp = tid >> 5;
    const int lane = tid & 31;
    const int wm   = warp >> 1;           // 0..3  (M: wm*32)
    const int wn   = warp & 1;            // 0..1  (N: wn*64, == head within block)

    if (tid < 128) { s_as[tid] = att_s[bx * 128 + tid]; s_ad[tid] = att_d[bx * 128 + tid]; }

    wmma::fragment<wmma::accumulator, 16, 16, 16, float> acc[2][4];
#pragma unroll
    for (int mt = 0; mt < 2; mt++)
#pragma unroll
        for (int nt = 0; nt < 4; nt++) wmma::fill_fragment(acc[mt][nt], 0.0f);

    const int nChunks = (KIN + BKF - 1) / BKF;   // 10
    for (int ch = 0; ch < nChunks; ch++) {
        const int k0 = ch * BKF;
        // ---- load & split A tile: 128 rows x 32 fp32 ----
#pragma unroll
        for (int it = 0; it < 4; it++) {
            int idx = tid + it * 256;             // 0..1023
            int row = idx >> 3;
            int c4  = (idx & 7) * 4;
            int gr = row0 + row, gk = k0 + c4;
            float4 v = make_float4(0.f, 0.f, 0.f, 0.f);
            if (gr < M && gk < KIN) v = *(const float4*)&X[(long long)gr * KIN + gk];
            __nv_bfloat16 h0 = __float2bfloat16(v.x);
            __nv_bfloat16 h1 = __float2bfloat16(v.y);
            __nv_bfloat16 h2 = __float2bfloat16(v.z);
            __nv_bfloat16 h3 = __float2bfloat16(v.w);
            __nv_bfloat16 l0 = __float2bfloat16(v.x - __bfloat162float(h0));
            __nv_bfloat16 l1 = __float2bfloat16(v.y - __bfloat162float(h1));
            __nv_bfloat16 l2 = __float2bfloat16(v.z - __bfloat162float(h2));
            __nv_bfloat16 l3 = __float2bfloat16(v.w - __bfloat162float(h3));
            int base = row * KP + c4;
            *(__nv_bfloat162*)&Ah[base]     = __nv_bfloat162(h0, h1);
            *(__nv_bfloat162*)&Ah[base + 2] = __nv_bfloat162(h2, h3);
            *(__nv_bfloat162*)&Al[base]     = __nv_bfloat162(l0, l1);
            *(__nv_bfloat162*)&Al[base + 2] = __nv_bfloat162(l2, l3);
        }
        // ---- load & split B tile: 32 k x 128 cols ----
#pragma unroll
        for (int it = 0; it < 4; it++) {
            int idx = tid + it * 256;
            int kk  = idx >> 5;
            int c4  = (idx & 31) * 4;
            int gk  = k0 + kk;
            float4 v = make_float4(0.f, 0.f, 0.f, 0.f);
            if (gk < KIN) v = *(const float4*)&W[(long long)gk * HC + bx * 128 + c4];
            __nv_bfloat16 h0 = __float2bfloat16(v.x);
            __nv_bfloat16 h1 = __float2bfloat16(v.y);
            __nv_bfloat16 h2 = __float2bfloat16(v.z);
            __nv_bfloat16 h3 = __float2bfloat16(v.w);
            __nv_bfloat16 l0 = __float2bfloat16(v.x - __bfloat162float(h0));
            __nv_bfloat16 l1 = __float2bfloat16(v.y - __bfloat162float(h1));
            __nv_bfloat16 l2 = __float2bfloat16(v.z - __bfloat162float(h2));
            __nv_bfloat16 l3 = __float2bfloat16(v.w - __bfloat162float(h3));
            int base = kk * NP + c4;
            *(__nv_bfloat162*)&Bh[base]     = __nv_bfloat162(h0, h1);
            *(__nv_bfloat162*)&Bh[base + 2] = __nv_bfloat162(h2, h3);
            *(__nv_bfloat162*)&Bl[base]     = __nv_bfloat162(l0, l1);
            *(__nv_bfloat162*)&Bl[base + 2] = __nv_bfloat162(l2, l3);
        }
        __syncthreads();

        // ---- mma over two k16 steps, three split-combos ----
#pragma unroll
        for (int ks = 0; ks < 2; ks++) {
            int kk16 = ks * 16;
            wmma::fragment<wmma::matrix_a, 16, 16, 16, __nv_bfloat16, wmma::row_major> ah[2], al[2];
            wmma::fragment<wmma::matrix_b, 16, 16, 16, __nv_bfloat16, wmma::row_major> bh[4], bl[4];
#pragma unroll
            for (int mt = 0; mt < 2; mt++) {
                int r = (wm * 32 + mt * 16) * KP + kk16;
                wmma::load_matrix_sync(ah[mt], &Ah[r], KP);
                wmma::load_matrix_sync(al[mt], &Al[r], KP);
            }
#pragma unroll
            for (int nt = 0; nt < 4; nt++) {
                int c = kk16 * NP + wn * 64 + nt * 16;
                wmma::load_matrix_sync(bh[nt], &Bh[c], NP);
                wmma::load_matrix_sync(bl[nt], &Bl[c], NP);
            }
#pragma unroll
            for (int mt = 0; mt < 2; mt++)
#pragma unroll
                for (int nt = 0; nt < 4; nt++) {
                    wmma::mma_sync(acc[mt][nt], ah[mt], bh[nt], acc[mt][nt]);
                    wmma::mma_sync(acc[mt][nt], ah[mt], bl[nt], acc[mt][nt]);
                    wmma::mma_sync(acc[mt][nt], al[mt], bh[nt], acc[mt][nt]);
                }
        }
        __syncthreads();
    }

    // ---- epilogue: per-warp smem staging, global store + fused att dots ----
    float* eb = (float*)smem_raw + warp * 16 * 68;   // 16 rows x 68 floats per warp
#pragma unroll
    for (int mt = 0; mt < 2; mt++) {
#pragma unroll
        for (int nt = 0; nt < 4; nt++)
            wmma::store_matrix_sync(&eb[nt * 16], acc[mt][nt], 68, wmma::mem_row_major);
        __syncwarp();
        int r  = lane >> 1;
        int chh = (lane & 1) * 32;
        int gr = row0 + wm * 32 + mt * 16 + r;
        float s = 0.f, d = 0.f;
#pragma unroll
        for (int j = 0; j < 8; j++) {
            float4 v = *(float4*)&eb[r * 68 + chh + j * 4];
            int cb = wn * 64 + chh + j * 4;   // col within block's 128
            s += v.x * s_as[cb] + v.y * s_as[cb + 1] + v.z * s_as[cb + 2] + v.w * s_as[cb + 3];
            d += v.x * s_ad[cb] + v.y * s_ad[cb + 1] + v.z * s_ad[cb + 2] + v.w * s_ad[cb + 3];
            if (gr < M)
                *(float4*)&g_h[(long long)gr * HC + bx * 128 + cb] = v;
        }
        s += __shfl_xor_sync(0xffffffffu, s, 1);
        d += __shfl_xor_sync(0xffffffffu, d, 1);
        if ((lane & 1) == 0 && gr < M) {
            g_asrc[gr * 4 + bx * 2 + wn] = s;
            g_adst[gr * 4 + bx * 2 + wn] = d;
        }
        __syncwarp();
    }
}

// ---------------- 2: per-edge exp(leaky(logit)) + degree count ----------------
// Softmax shift dropped: logits are O(10), exp() is safe; ratios identical.
__global__ void edge_exp_count_kernel(const int* __restrict__ ei, int E, int M) {
    int i = blockIdx.x * blockDim.x + threadIdx.x;
    int total = E + M;
    if (i >= total) return;
    int s, d;
    if (i < E) { s = ei[i]; d = ei[E + i]; }
    else       { s = d = i - E; }
    float4 as = ((const float4*)g_asrc)[s];
    float4 ad = ((const float4*)g_adst)[d];
    float e0 = as.x + ad.x, e1 = as.y + ad.y, e2 = as.z + ad.z, e3 = as.w + ad.w;
    e0 = e0 > 0.f ? e0 : 0.2f * e0;
    e1 = e1 > 0.f ? e1 : 0.2f * e1;
    e2 = e2 > 0.f ? e2 : 0.2f * e2;
    e3 = e3 > 0.f ? e3 : 0.2f * e3;
    ((float4*)g_e)[i] = make_float4(__expf(e0), __expf(e1), __expf(e2), __expf(e3));
    atomicAdd(&g_count[d], 1);
}

// ---------------- 3: 2-level exclusive scan of g_count ----------------
__global__ void scan1_kernel(int M) {                     // block=1024
    __shared__ int sh[2][1024];
    int i = blockIdx.x * 1024 + threadIdx.x;
    int v = (i < M) ? g_count[i] : 0;
    int buf = 0;
    sh[0][threadIdx.x] = v;
    __syncthreads();
#pragma unroll
    for (int off = 1; off < 1024; off <<= 1) {
        int nv = sh[buf][threadIdx.x];
        if (threadIdx.x >= off) nv += sh[buf][threadIdx.x - off];
        sh[1 - buf][threadIdx.x] = nv;
        buf = 1 - buf;
        __syncthreads();
    }
    int incl = sh[buf][threadIdx.x];
    if (i < M) g_scanex[i] = incl - v;
    if (threadIdx.x == 1023) g_bsum[blockIdx.x] = incl;
}

__global__ void scan2_kernel(int nb) {                    // 1 thread
    int run = 0;
    for (int b = 0; b < nb; b++) { int t = g_bsum[b]; g_bsum[b] = run; run += t; }
}

__global__ void scan3_kernel(int M) {
    int i = blockIdx.x * blockDim.x + threadIdx.x;
    if (i >= M) return;
    int off = g_scanex[i] + g_bsum[i >> 10];
    g_rowoff[i] = off;
    g_cursor[i] = off;
}

// ---------------- 4: CSR fill ----------------
__global__ void edge_fill_kernel(const int* __restrict__ ei, int E, int M) {
    int i = blockIdx.x * blockDim.x + threadIdx.x;
    int total = E + M;
    if (i >= total) return;
    int s, d;
    if (i < E) { s = ei[i]; d = ei[E + i]; }
    else       { s = d = i - E; }
    float4 ee = ((const float4*)g_e)[i];
    int pos = atomicAdd(&g_cursor[d], 1);
    g_csrc[pos] = s;
    g_cee[pos]  = ee;
}

// ---------------- 5: gather-aggregate (warp per node) + softmax denom + bias + leaky + pool ----------------
__global__ void aggregate_kernel(const int* __restrict__ batch,
                                 const float* __restrict__ bias, int M) {
    int w = blockIdx.x * (blockDim.x >> 5) + (threadIdx.x >> 5);
    if (w >= M) return;
    int lane = threadIdx.x & 31;
    int start = g_rowoff[w];
    int end   = start + g_count[w];
    int hsel  = lane >> 3;                      // head for this thread's 8 channels

    float acc[8];
#pragma unroll
    for (int k = 0; k < 8; k++) acc[k] = 0.0f;
    float wsum = 0.0f;

    int src = 0; float4 ee = make_float4(0, 0, 0, 0);
    if (start < end) { src = g_csrc[start]; ee = g_cee[start]; }
    for (int j = start; j < end; j++) {
        int nsrc = 0; float4 nee = ee;
        if (j + 1 < end) { nsrc = g_csrc[j + 1]; nee = g_cee[j + 1]; }
        const float4* hp = (const float4*)&g_h[(long long)src * HC + lane * 8];
        float4 h0 = hp[0], h1 = hp[1];
        float wgt = (hsel == 0) ? ee.x : (hsel == 1) ? ee.y : (hsel == 2) ? ee.z : ee.w;
        wsum += wgt;
        acc[0] += h0.x * wgt; acc[1] += h0.y * wgt;
        acc[2] += h0.z * wgt; acc[3] += h0.w * wgt;
        acc[4] += h1.x * wgt; acc[5] += h1.y * wgt;
        acc[6] += h1.z * wgt; acc[7] += h1.w * wgt;
        src = nsrc; ee = nee;
    }

    float inv = 1.0f / wsum;
    int b = batch[w];
    float* pp = &g_pool[b * HC + lane * 8];
#pragma unroll
    for (int k = 0; k < 8; k++) {
        float v = acc[k] * inv + bias[lane * 8 + k];
        v = v > 0.f ? v : 0.01f * v;
        atomicAdd(&pp[k], v);
    }
    if (lane == 0) atomicAdd(&g_cnt[b], 1.0f);
}

// ---------------- 6: mean + final FC ----------------
__global__ void final_fc_kernel(const float* __restrict__ fc1_w,
                                const float* __restrict__ fc1_b,
                                float* __restrict__ out) {
    __shared__ float p[HC];
    int g = blockIdx.x;
    int tid = threadIdx.x;   // 256
    float inv = 1.0f / fmaxf(g_cnt[g], 1.0f);
    p[tid] = g_pool[g * HC + tid] * inv;
    __syncthreads();
#pragma unroll
    for (int j0 = 0; j0 < FOUT; j0 += 256) {
        int j = j0 + tid;
        float acc = fc1_b[j];
#pragma unroll 8
        for (int k = 0; k < HC; k++) acc += p[k] * fc1_w[k * FOUT + j];
        out[g * FOUT + j] = acc;
    }
}

// ---------------- launch ----------------
extern "C" void kernel_launch(void* const* d_in, const int* in_sizes, int n_in,
                              void* d_out, int out_size) {
    const float* x     = (const float*)d_in[0];
    const int*   ei    = (const int*)d_in[1];
    const int*   batch = (const int*)d_in[2];
    const float* lin_w = (const float*)d_in[3];
    const float* att_s = (const float*)d_in[4];
    const float* att_d = (const float*)d_in[5];
    const float* bias  = (const float*)d_in[6];
    const float* fc1_w = (const float*)d_in[7];
    const float* fc1_b = (const float*)d_in[8];
    float* out = (float*)d_out;

    int M = in_sizes[2];       // nodes
    int E = in_sizes[1] / 2;   // edges
    int total = E + M;

    int initN = M > GRAPHS * HC ? M : GRAPHS * HC;
    init_kernel<<<(initN + 255) / 256, 256>>>(M);

    dim3 ggrid(2, (M + BM - 1) / BM);
    gemm_h_kernel<<<ggrid, 256>>>(x, lin_w, att_s, att_d, M);

    edge_exp_count_kernel<<<(total + 255) / 256, 256>>>(ei, E, M);

    int nb = (M + 1023) / 1024;
    scan1_kernel<<<nb, 1024>>>(M);
    scan2_kernel<<<1, 1>>>(nb);
    scan3_kernel<<<(M + 255) / 256, 256>>>(M);

    edge_fill_kernel<<<(total + 255) / 256, 256>>>(ei, E, M);

    aggregate_kernel<<<(M * 32 + 255) / 256, 256>>>(batch, bias, M);

    final_fc_kernel<<<GRAPHS, 256>>>(fc1_w, fc1_b, out);
}

// round 4
// speedup vs baseline: 1.1795x; 1.1795x over previous
#include <cuda_runtime.h>
#include <cuda_bf16.h>

// Problem constants
#define NMAX   50000
#define EMAX   800000
#define TOTMAX (EMAX + NMAX)
#define GRAPHS 256
#define HC     256      // H*C
#define KIN    300      // n_in
#define FOUT   768      // nout

// ---------------- scratch (device globals; no allocation) ----------------
__device__ float  g_h[NMAX * HC];          // node features after linear [N,256]
__device__ float  g_asrc[NMAX * 4];        // per-node src attention logits [N,4]
__device__ float  g_adst[NMAX * 4];        // per-node dst attention logits [N,4]
__device__ float  g_e[TOTMAX * 4];         // per-edge exp(leaky(logit)) [E+N,4]
__device__ int    g_count[NMAX];           // in-degree (incl self-loop)
__device__ int    g_scanex[NMAX];          // per-chunk exclusive scan
__device__ int    g_bsum[64];              // chunk totals -> chunk offsets
__device__ int    g_rowoff[NMAX];          // CSR row offsets
__device__ int    g_cursor[NMAX];          // fill cursors
__device__ int    g_csrc[TOTMAX];          // CSR-ordered src ids
__device__ float4 g_cee[TOTMAX];           // CSR-ordered exp weights (per head)
__device__ float  g_pool[GRAPHS * HC];     // per-graph sums [G,256]
__device__ float  g_pooled[GRAPHS * HC];   // normalized pooled features
__device__ float  g_cnt[GRAPHS];           // per-graph node counts

// ---------------- 0: init scratch ----------------
__global__ void init_kernel(int M) {
    int i = blockIdx.x * blockDim.x + threadIdx.x;
    if (i < M)            g_count[i] = 0;
    if (i < GRAPHS * HC)  g_pool[i]  = 0.0f;
    if (i < GRAPHS)       g_cnt[i]   = 0.0f;
}

// ---------------- 1: h = x @ lin_w (+ fused attention dots), fp32 SIMT ----------------
// 128x128 tile, BK=8, 256 threads, 8x8 per thread (2x2 blocks of 4x4).
#define BM 128
#define BN 128
#define BK 8
__global__ __launch_bounds__(256, 2)
void gemm_h_kernel(const float* __restrict__ X,
                   const float* __restrict__ W,
                   const float* __restrict__ att_s,
                   const float* __restrict__ att_d,
                   int M) {
    __shared__ float As[BK][BM];
    __shared__ float Bs[BK][BN];
    __shared__ float s_as[BN], s_ad[BN];

    const int bx   = blockIdx.x;              // 0..1 -> N offset bx*128 (heads bx*2, bx*2+1)
    const int row0 = blockIdx.y * BM;
    const int tid  = threadIdx.x;
    const int tx   = tid & 15;
    const int ty   = tid >> 4;

    if (tid < BN) { s_as[tid] = att_s[bx * BN + tid]; s_ad[tid] = att_d[bx * BN + tid]; }

    float acc[2][2][4][4];
#pragma unroll
    for (int a = 0; a < 2; a++)
#pragma unroll
        for (int b = 0; b < 2; b++)
#pragma unroll
            for (int i = 0; i < 4; i++)
#pragma unroll
                for (int j = 0; j < 4; j++) acc[a][b][i][j] = 0.0f;

    const int arow  = tid >> 1;             // 0..127
    const int akb   = (tid & 1) * 4;        // 0 or 4
    const int bkk   = tid >> 5;             // 0..7
    const int bcol  = (tid & 31) * 4;       // 0..124

    for (int k0 = 0; k0 < KIN; k0 += BK) {
        {
            int gr = row0 + arow, gk = k0 + akb;
            float4 a4 = make_float4(0.f, 0.f, 0.f, 0.f);
            if (gr < M && gk < KIN) a4 = *(const float4*)&X[gr * KIN + gk];
            As[akb + 0][arow] = a4.x;
            As[akb + 1][arow] = a4.y;
            As[akb + 2][arow] = a4.z;
            As[akb + 3][arow] = a4.w;
        }
        {
            int gk = k0 + bkk;
            float4 b4 = make_float4(0.f, 0.f, 0.f, 0.f);
            if (gk < KIN) b4 = *(const float4*)&W[gk * HC + bx * BN + bcol];
            *(float4*)&Bs[bkk][bcol] = b4;
        }
        __syncthreads();
#pragma unroll
        for (int kk = 0; kk < BK; kk++) {
            float4 a0 = *(const float4*)&As[kk][ty * 4];
            float4 a1 = *(const float4*)&As[kk][64 + ty * 4];
            float4 b0 = *(const float4*)&Bs[kk][tx * 4];
            float4 b1 = *(const float4*)&Bs[kk][64 + tx * 4];
            float av[2][4] = {{a0.x, a0.y, a0.z, a0.w}, {a1.x, a1.y, a1.z, a1.w}};
            float bv[2][4] = {{b0.x, b0.y, b0.z, b0.w}, {b1.x, b1.y, b1.z, b1.w}};
#pragma unroll
            for (int a = 0; a < 2; a++)
#pragma unroll
                for (int b = 0; b < 2; b++)
#pragma unroll
                    for (int i = 0; i < 4; i++)
#pragma unroll
                        for (int j = 0; j < 4; j++)
                            acc[a][b][i][j] += av[a][i] * bv[b][j];
        }
        __syncthreads();
    }

    // epilogue: store h + fused attention dots
#pragma unroll
    for (int a = 0; a < 2; a++) {
#pragma unroll
        for (int i = 0; i < 4; i++) {
            int gr = row0 + a * 64 + ty * 4 + i;
            bool ok = gr < M;
#pragma unroll
            for (int b = 0; b < 2; b++) {
                if (ok) {
                    *(float4*)&g_h[gr * HC + bx * BN + b * 64 + tx * 4] =
                        make_float4(acc[a][b][i][0], acc[a][b][i][1],
                                    acc[a][b][i][2], acc[a][b][i][3]);
                }
                float s = 0.f, d = 0.f;
#pragma unroll
                for (int j = 0; j < 4; j++) {
                    s += acc[a][b][i][j] * s_as[b * 64 + tx * 4 + j];
                    d += acc[a][b][i][j] * s_ad[b * 64 + tx * 4 + j];
                }
#pragma unroll
                for (int off = 8; off > 0; off >>= 1) {
                    s += __shfl_down_sync(0xffffffffu, s, off, 16);
                    d += __shfl_down_sync(0xffffffffu, d, off, 16);
                }
                if (ok && tx == 0) {
                    g_asrc[gr * 4 + bx * 2 + b] = s;
                    g_adst[gr * 4 + bx * 2 + b] = d;
                }
            }
        }
    }
}

// ---------------- 2: per-edge exp(leaky(logit)) + degree count ----------------
// Softmax shift dropped: logits are O(10), exp() is safe; ratios identical.
__global__ void edge_exp_count_kernel(const int* __restrict__ ei, int E, int M) {
    int i = blockIdx.x * blockDim.x + threadIdx.x;
    int total = E + M;
    if (i >= total) return;
    int s, d;
    if (i < E) { s = ei[i]; d = ei[E + i]; }
    else       { s = d = i - E; }
    float4 as = ((const float4*)g_asrc)[s];
    float4 ad = ((const float4*)g_adst)[d];
    float e0 = as.x + ad.x, e1 = as.y + ad.y, e2 = as.z + ad.z, e3 = as.w + ad.w;
    e0 = e0 > 0.f ? e0 : 0.2f * e0;
    e1 = e1 > 0.f ? e1 : 0.2f * e1;
    e2 = e2 > 0.f ? e2 : 0.2f * e2;
    e3 = e3 > 0.f ? e3 : 0.2f * e3;
    ((float4*)g_e)[i] = make_float4(__expf(e0), __expf(e1), __expf(e2), __expf(e3));
    atomicAdd(&g_count[d], 1);
}

// ---------------- 3: 2-level exclusive scan of g_count ----------------
__global__ void scan1_kernel(int M) {                     // block=1024
    __shared__ int sh[2][1024];
    int i = blockIdx.x * 1024 + threadIdx.x;
    int v = (i < M) ? g_count[i] : 0;
    int buf = 0;
    sh[0][threadIdx.x] = v;
    __syncthreads();
#pragma unroll
    for (int off = 1; off < 1024; off <<= 1) {
        int nv = sh[buf][threadIdx.x];
        if (threadIdx.x >= off) nv += sh[buf][threadIdx.x - off];
        sh[1 - buf][threadIdx.x] = nv;
        buf = 1 - buf;
        __syncthreads();
    }
    int incl = sh[buf][threadIdx.x];
    if (i < M) g_scanex[i] = incl - v;
    if (threadIdx.x == 1023) g_bsum[blockIdx.x] = incl;
}

__global__ void scan2_kernel(int nb) {                    // 1 thread
    int run = 0;
    for (int b = 0; b < nb; b++) { int t = g_bsum[b]; g_bsum[b] = run; run += t; }
}

__global__ void scan3_kernel(int M) {
    int i = blockIdx.x * blockDim.x + threadIdx.x;
    if (i >= M) return;
    int off = g_scanex[i] + g_bsum[i >> 10];
    g_rowoff[i] = off;
    g_cursor[i] = off;
}

// ---------------- 4: CSR fill ----------------
__global__ void edge_fill_kernel(const int* __restrict__ ei, int E, int M) {
    int i = blockIdx.x * blockDim.x + threadIdx.x;
    int total = E + M;
    if (i >= total) return;
    int s, d;
    if (i < E) { s = ei[i]; d = ei[E + i]; }
    else       { s = d = i - E; }
    float4 ee = ((const float4*)g_e)[i];
    int pos = atomicAdd(&g_cursor[d], 1);
    g_csrc[pos] = s;
    g_cee[pos]  = ee;
}

// ---------------- 5: gather-aggregate (warp per node) + denom + bias + leaky + pool ----------------
__global__ void aggregate_kernel(const int* __restrict__ batch,
                                 const float* __restrict__ bias, int M) {
    int w = blockIdx.x * (blockDim.x >> 5) + (threadIdx.x >> 5);
    if (w >= M) return;
    int lane = threadIdx.x & 31;
    int start = g_rowoff[w];
    int end   = start + g_count[w];
    int hsel  = lane >> 3;                      // head for this thread's 8 channels

    float acc[8];
#pragma unroll
    for (int k = 0; k < 8; k++) acc[k] = 0.0f;
    float wsum = 0.0f;

    int src = 0; float4 ee = make_float4(0, 0, 0, 0);
    if (start < end) { src = g_csrc[start]; ee = g_cee[start]; }
    for (int j = start; j < end; j++) {
        int nsrc = 0; float4 nee = ee;
        if (j + 1 < end) { nsrc = g_csrc[j + 1]; nee = g_cee[j + 1]; }
        const float4* hp = (const float4*)&g_h[(long long)src * HC + lane * 8];
        float4 h0 = hp[0], h1 = hp[1];
        float wgt = (hsel == 0) ? ee.x : (hsel == 1) ? ee.y : (hsel == 2) ? ee.z : ee.w;
        wsum += wgt;
        acc[0] += h0.x * wgt; acc[1] += h0.y * wgt;
        acc[2] += h0.z * wgt; acc[3] += h0.w * wgt;
        acc[4] += h1.x * wgt; acc[5] += h1.y * wgt;
        acc[6] += h1.z * wgt; acc[7] += h1.w * wgt;
        src = nsrc; ee = nee;
    }

    float inv = 1.0f / wsum;
    int b = batch[w];
    float* pp = &g_pool[b * HC + lane * 8];
#pragma unroll
    for (int k = 0; k < 8; k++) {
        float v = acc[k] * inv + bias[lane * 8 + k];
        v = v > 0.f ? v : 0.01f * v;
        atomicAdd(&pp[k], v);
    }
    if (lane == 0) atomicAdd(&g_cnt[b], 1.0f);
}

// ---------------- 6a: normalize pooled sums ----------------
__global__ void pool_norm_kernel() {
    int i = blockIdx.x * blockDim.x + threadIdx.x;
    if (i >= GRAPHS * HC) return;
    int g = i >> 8;
    g_pooled[i] = g_pool[i] / fmaxf(g_cnt[g], 1.0f);
}

// ---------------- 6b: out = pooled @ fc1_w + fc1_b, tiled ----------------
// 32 graphs x 64 outs per block, 256 threads, 8 outs per thread.
#define FBM 32
#define FBN 64
#define SPP 260   // padded pooled row stride (floats), 16B-aligned, kills bank conflicts
__global__ __launch_bounds__(256)
void fc_kernel(const float* __restrict__ fc1_w,
               const float* __restrict__ fc1_b,
               float* __restrict__ out) {
    __shared__ float sp[FBM * SPP];   // 32 pooled rows
    __shared__ float sw[32][FBN];     // W tile
    const int g0  = blockIdx.y * FBM;
    const int n0  = blockIdx.x * FBN;
    const int tid = threadIdx.x;

    // load 32 pooled rows (256 floats each)
#pragma unroll
    for (int it = 0; it < 8; it++) {
        int i = tid + it * 256;           // 0..2047 float4 slots
        int r = i >> 6;                   // /64 float4s per row
        int c = (i & 63) * 4;
        *(float4*)&sp[r * SPP + c] = *(const float4*)&g_pooled[(g0 + r) * HC + c];
    }

    const int row = tid >> 3;             // 0..31
    const int cg  = (tid & 7) * 8;        // 0..56
    float acc[8];
#pragma unroll
    for (int j = 0; j < 8; j++) acc[j] = 0.0f;

    for (int k0 = 0; k0 < HC; k0 += 32) {
        __syncthreads();
        // load W tile 32 x 64
#pragma unroll
        for (int it = 0; it < 2; it++) {
            int i = tid + it * 256;       // 0..511 float4 slots
            int r = i >> 4;               // /16 float4s per row
            int c = (i & 15) * 4;
            *(float4*)&sw[r][c] = *(const float4*)&fc1_w[(k0 + r) * FOUT + n0 + c];
        }
        __syncthreads();
#pragma unroll
        for (int kk = 0; kk < 32; kk++) {
            float p = sp[row * SPP + k0 + kk];
            float4 w0 = *(const float4*)&sw[kk][cg];
            float4 w1 = *(const float4*)&sw[kk][cg + 4];
            acc[0] += p * w0.x; acc[1] += p * w0.y;
            acc[2] += p * w0.z; acc[3] += p * w0.w;
            acc[4] += p * w1.x; acc[5] += p * w1.y;
            acc[6] += p * w1.z; acc[7] += p * w1.w;
        }
    }
#pragma unroll
    for (int j = 0; j < 8; j++) acc[j] += fc1_b[n0 + cg + j];
    *(float4*)&out[(g0 + row) * FOUT + n0 + cg]     = make_float4(acc[0], acc[1], acc[2], acc[3]);
    *(float4*)&out[(g0 + row) * FOUT + n0 + cg + 4] = make_float4(acc[4], acc[5], acc[6], acc[7]);
}

// ---------------- launch ----------------
extern "C" void kernel_launch(void* const* d_in, const int* in_sizes, int n_in,
                              void* d_out, int out_size) {
    const float* x     = (const float*)d_in[0];
    const int*   ei    = (const int*)d_in[1];
    const int*   batch = (const int*)d_in[2];
    const float* lin_w = (const float*)d_in[3];
    const float* att_s = (const float*)d_in[4];
    const float* att_d = (const float*)d_in[5];
    const float* bias  = (const float*)d_in[6];
    const float* fc1_w = (const float*)d_in[7];
    const float* fc1_b = (const float*)d_in[8];
    float* out = (float*)d_out;

    int M = in_sizes[2];       // nodes
    int E = in_sizes[1] / 2;   // edges
    int total = E + M;

    int initN = M > GRAPHS * HC ? M : GRAPHS * HC;
    init_kernel<<<(initN + 255) / 256, 256>>>(M);

    dim3 ggrid(2, (M + BM - 1) / BM);
    gemm_h_kernel<<<ggrid, 256>>>(x, lin_w, att_s, att_d, M);

    edge_exp_count_kernel<<<(total + 255) / 256, 256>>>(ei, E, M);

    int nb = (M + 1023) / 1024;
    scan1_kernel<<<nb, 1024>>>(M);
    scan2_kernel<<<1, 1>>>(nb);
    scan3_kernel<<<(M + 255) / 256, 256>>>(M);

    edge_fill_kernel<<<(total + 255) / 256, 256>>>(ei, E, M);

    aggregate_kernel<<<(M * 32 + 255) / 256, 256>>>(batch, bias, M);

    pool_norm_kernel<<<(GRAPHS * HC + 255) / 256, 256>>>();

    dim3 fgrid(FOUT / FBN, GRAPHS / FBM);
    fc_kernel<<<fgrid, 256>>>(fc1_w, fc1_b, out);
}